// round 7
// baseline (speedup 1.0000x reference)
#include <cuda_runtime.h>
#include <cuda_bf16.h>

#define JNT 24
#define EPSF 1e-6f
#define SH_C0 0.28209479177387814f
#define SH_C1 0.4886025119029199f
#define C20 ( 1.0925484305920792f)
#define C21 (-1.0925484305920792f)
#define C22 ( 0.31539156525252005f)
#define C23 (-1.0925484305920792f)
#define C24 ( 0.5462742152960396f)

#define THREADS 256

__device__ __forceinline__ float frcp(float x) {
    float r; asm("rcp.approx.ftz.f32 %0, %1;" : "=f"(r) : "f"(x)); return r;
}

// Shared: 6 float4 per joint
//  q0 : (-r00, -r01, -r02, L0-t0)
//  q1 : (-r10, -r11, -r12, L1-t1)
//  q2 : (-r20, -r21, -r22, L2-t2)
//  q3 : (t0, t1, t2, base)        base = SH_C0*f0 + 0.5 - C22*f6
//  q4 : (f1', f2', f3', f4')      pre-scaled SH features
//  q5 : (f5', f6'', f7', f8')     f6'' = 3*C22*f6
__global__ __launch_bounds__(THREADS)
void shcaster_kernel(const float* __restrict__ xyz,
                     const float* __restrict__ vdir,
                     const float* __restrict__ T,   // [J,4,4]
                     const float* __restrict__ F,   // [J,9]
                     const float* __restrict__ L,   // [J,3]
                     float* __restrict__ out,       // [2*N*3]
                     int N)
{
    __shared__ __align__(16) float4 sJ[JNT][6];

    const int tid = threadIdx.x;
    if (tid < JNT * 6) {
        const int j = tid / 6, k = tid % 6;
        float4 q;
        if (k < 3) {
            const float* r = T + j * 16 + k * 4;   // r0 r1 r2 t
            q = make_float4(-r[0], -r[1], -r[2], L[j * 3 + k] - r[3]);
        } else if (k == 3) {
            const float base = fmaf(SH_C0, F[j * 9 + 0], 0.5f) - C22 * F[j * 9 + 6];
            q = make_float4(T[j * 16 + 3], T[j * 16 + 7], T[j * 16 + 11], base);
        } else if (k == 4) {
            q = make_float4(-SH_C1 * F[j * 9 + 1],
                             SH_C1 * F[j * 9 + 2],
                            -SH_C1 * F[j * 9 + 3],
                             C20   * F[j * 9 + 4]);
        } else {
            q = make_float4( C21        * F[j * 9 + 5],
                             3.f * C22  * F[j * 9 + 6],
                             C23        * F[j * 9 + 7],
                             C24        * F[j * 9 + 8]);
        }
        sJ[j][k] = q;
    }
    __syncthreads();

    const int i = blockIdx.x * blockDim.x + tid;
    if (i >= N) return;

    const float x0 = xyz[3 * i + 0];
    const float x1 = xyz[3 * i + 1];
    const float x2 = xyz[3 * i + 2];
    const float v0 = vdir[3 * i + 0];
    const float v1 = vdir[3 * i + 1];
    const float v2 = vdir[3 * i + 2];

    float wsum = 0.f;
    float ta0 = 0.f, ta1 = 0.f, ta2 = 0.f;            // sum w * t
    float m00 = 0.f, m01 = 0.f, m02 = 0.f;            // sum w * (-R)
    float m10 = 0.f, m11 = 0.f, m12 = 0.f;
    float m20 = 0.f, m21 = 0.f, m22 = 0.f;

#pragma unroll
    for (int j = 0; j < JNT; j++) {
        const float4 q0 = sJ[j][0];
        const float4 q1 = sJ[j][1];
        const float4 q2 = sJ[j][2];
        const float4 q3 = sJ[j][3];
        const float4 q4 = sJ[j][4];
        const float4 q5 = sJ[j][5];

        // d = (L - t) - R x  directly (negated R stored in shared)
        const float d0 = fmaf(q0.x, x0, fmaf(q0.y, x1, fmaf(q0.z, x2, q0.w)));
        const float d1 = fmaf(q1.x, x0, fmaf(q1.y, x1, fmaf(q1.z, x2, q1.w)));
        const float d2 = fmaf(q2.x, x0, fmaf(q2.y, x1, fmaf(q2.z, x2, q2.w)));

        const float zz = d2 * d2;
        const float l2  = fmaf(d0, d0, fmaf(d1, d1, zz));
        const float inv = rsqrtf(l2);
        const float inv2 = inv * inv;

        // SH dot in unnormalized d-space:
        // rad = base + (lin . d) * inv + quad(d) * inv^2
        const float linD = fmaf(q4.x, d1, fmaf(q4.y, d2, q4.z * d0));
        const float xy = d0 * d1;
        const float yz = d1 * d2;
        const float xz = d0 * d2;
        const float pm = fmaf(d0, d0, -(d1 * d1));   // x^2 - y^2
        const float quadD = fmaf(q4.w, xy,
                            fmaf(q5.x, yz,
                            fmaf(q5.y, zz,
                            fmaf(q5.z, xz, q5.w * pm))));
        const float rad = fmaf(linD, inv, fmaf(quadD, inv2, q3.w));

        // weight: r = max(relu(rad), EPS) = max(rad, EPS)
        const float r = fmaxf(rad, EPSF);
        const float len = l2 * inv;
        const float w = fmaxf(fmaf(-len, frcp(r), 1.0f), 0.f);

        wsum += w;
        ta0 = fmaf(w, q3.x, ta0);
        ta1 = fmaf(w, q3.y, ta1);
        ta2 = fmaf(w, q3.z, ta2);
        m00 = fmaf(w, q0.x, m00); m01 = fmaf(w, q0.y, m01); m02 = fmaf(w, q0.z, m02);
        m10 = fmaf(w, q1.x, m10); m11 = fmaf(w, q1.y, m11); m12 = fmaf(w, q1.z, m12);
        m20 = fmaf(w, q2.x, m20); m21 = fmaf(w, q2.y, m21); m22 = fmaf(w, q2.z, m22);
    }

    const float ic = frcp(fmaxf(wsum, EPSF));
    const bool valid = wsum > EPSF;

    // s = (sum w R) x + sum w t = tacc - (mneg x)
    const float mx0 = fmaf(m00, x0, fmaf(m01, x1, m02 * x2));
    const float mx1 = fmaf(m10, x0, fmaf(m11, x1, m12 * x2));
    const float mx2 = fmaf(m20, x0, fmaf(m21, x1, m22 * x2));
    const float o0 = valid ? (ta0 - mx0) * ic : x0;
    const float o1 = valid ? (ta1 - mx1) * ic : x1;
    const float o2 = valid ? (ta2 - mx2) * ic : x2;

    // vd_out = (sum w R) v / c = (mneg v) * (-ic)
    const float nic = -ic;
    const float e0 = fmaf(m00, v0, fmaf(m01, v1, m02 * v2)) * nic;
    const float e1 = fmaf(m10, v0, fmaf(m11, v1, m12 * v2)) * nic;
    const float e2 = fmaf(m20, v0, fmaf(m21, v1, m22 * v2)) * nic;
    const float g0 = valid ? e0 : v0;
    const float g1 = valid ? e1 : v1;
    const float g2 = valid ? e2 : v2;

    out[3 * i + 0] = o0;
    out[3 * i + 1] = o1;
    out[3 * i + 2] = o2;
    float* out2 = out + (size_t)3 * N;
    out2[3 * i + 0] = g0;
    out2[3 * i + 1] = g1;
    out2[3 * i + 2] = g2;
}

extern "C" void kernel_launch(void* const* d_in, const int* in_sizes, int n_in,
                              void* d_out, int out_size)
{
    const float* xyz  = (const float*)d_in[0];
    const float* vdir = (const float*)d_in[1];
    const float* T    = (const float*)d_in[2];
    const float* F    = (const float*)d_in[3];
    const float* L    = (const float*)d_in[4];
    float* out        = (float*)d_out;

    const int N = in_sizes[0] / 3;
    const int blocks = (N + THREADS - 1) / THREADS;
    shcaster_kernel<<<blocks, THREADS>>>(xyz, vdir, T, F, L, out, N);
}

// round 8
// speedup vs baseline: 1.0918x; 1.0918x over previous
#include <cuda_runtime.h>
#include <cuda_bf16.h>

#define JNT 24
#define EPSF 1e-6f
#define SH_C0 0.28209479177387814f
#define SH_C1 0.4886025119029199f
#define C20 ( 1.0925484305920792f)
#define C21 (-1.0925484305920792f)
#define C22 ( 0.31539156525252005f)
#define C23 (-1.0925484305920792f)
#define C24 ( 0.5462742152960396f)

#define THREADS 256

typedef unsigned long long u64;

__device__ __forceinline__ float frcp(float x) {
    float r; asm("rcp.approx.ftz.f32 %0, %1;" : "=f"(r) : "f"(x)); return r;
}
__device__ __forceinline__ u64 pk2(float lo, float hi) {
    u64 r; asm("mov.b64 %0, {%1, %2};" : "=l"(r) : "f"(lo), "f"(hi)); return r;
}
__device__ __forceinline__ void upk2(float& lo, float& hi, u64 v) {
    asm("mov.b64 {%0, %1}, %2;" : "=f"(lo), "=f"(hi) : "l"(v));
}
__device__ __forceinline__ u64 ffma2(u64 a, u64 b, u64 c) {
    u64 d; asm("fma.rn.f32x2 %0, %1, %2, %3;" : "=l"(d) : "l"(a), "l"(b), "l"(c)); return d;
}

// Shared: 6 float4 per joint (pair-oriented layout)
//  f0 : (-r00, -r10, -r01, -r11)
//  f1 : (-r02, -r12, L0-t0, L1-t1)
//  f2 : (-r20, -r21, -r22, t0)
//  f3 : (t1, t2, L2-t2, base)      base = SH_C0*f0 + 0.5 - C22*f6
//  f4 : (f1', f2', f3', f4')       pre-scaled SH features
//  f5 : (f5', f6'', f7', f8')      f6'' = 3*C22*f6
__global__ __launch_bounds__(THREADS)
void shcaster_kernel(const float* __restrict__ xyz,
                     const float* __restrict__ vdir,
                     const float* __restrict__ T,   // [J,4,4]
                     const float* __restrict__ F,   // [J,9]
                     const float* __restrict__ L,   // [J,3]
                     float* __restrict__ out,       // [2*N*3]
                     int N)
{
    __shared__ __align__(16) float4 sJ[JNT][6];

    const int tid = threadIdx.x;
    if (tid < JNT * 6) {
        const int j = tid / 6, k = tid % 6;
        const float* t = T + j * 16;
        float4 q;
        if (k == 0) {
            q = make_float4(-t[0], -t[4], -t[1], -t[5]);
        } else if (k == 1) {
            q = make_float4(-t[2], -t[6], L[j*3+0] - t[3], L[j*3+1] - t[7]);
        } else if (k == 2) {
            q = make_float4(-t[8], -t[9], -t[10], t[3]);
        } else if (k == 3) {
            const float base = fmaf(SH_C0, F[j*9+0], 0.5f) - C22 * F[j*9+6];
            q = make_float4(t[7], t[11], L[j*3+2] - t[11], base);
        } else if (k == 4) {
            q = make_float4(-SH_C1 * F[j*9+1],
                             SH_C1 * F[j*9+2],
                            -SH_C1 * F[j*9+3],
                             C20   * F[j*9+4]);
        } else {
            q = make_float4( C21       * F[j*9+5],
                             3.f * C22 * F[j*9+6],
                             C23       * F[j*9+7],
                             C24       * F[j*9+8]);
        }
        sJ[j][k] = q;
    }
    __syncthreads();

    const int i = blockIdx.x * blockDim.x + tid;
    if (i >= N) return;

    const float x0 = xyz[3 * i + 0];
    const float x1 = xyz[3 * i + 1];
    const float x2 = xyz[3 * i + 2];
    const float v0 = vdir[3 * i + 0];
    const float v1 = vdir[3 * i + 1];
    const float v2 = vdir[3 * i + 2];

    // broadcast-packed point coords (once)
    const u64 X0 = pk2(x0, x0);
    const u64 X1 = pk2(x1, x1);
    const u64 X2 = pk2(x2, x2);

    float wsum = 0.f;
    u64 A0 = 0ull;   // {m00, m10}   (m = sum w * -R)
    u64 A1 = 0ull;   // {m01, m11}
    u64 A2 = 0ull;   // {m02, m12}
    u64 A3 = 0ull;   // {m20, m21}
    u64 A4 = 0ull;   // {m22, ta0}   (ta = sum w * t)
    u64 A5 = 0ull;   // {ta1, ta2}

#pragma unroll
    for (int j = 0; j < JNT; j++) {
        const float4 f0 = sJ[j][0];
        const float4 f1 = sJ[j][1];
        const float4 f2 = sJ[j][2];
        const float4 f3 = sJ[j][3];
        const float4 f4 = sJ[j][4];
        const float4 f5 = sJ[j][5];

        const u64 c00 = pk2(f0.x, f0.y);   // {-r00,-r10}
        const u64 c01 = pk2(f0.z, f0.w);   // {-r01,-r11}
        const u64 c02 = pk2(f1.x, f1.y);   // {-r02,-r12}
        const u64 cL  = pk2(f1.z, f1.w);   // {L0-t0, L1-t1}

        // d01 = (L-t) - R x   (lanes: d0, d1)
        const u64 d01 = ffma2(c00, X0, ffma2(c01, X1, ffma2(c02, X2, cL)));
        float d0, d1;
        upk2(d0, d1, d01);
        // d2 scalar
        const float d2 = fmaf(f2.x, x0, fmaf(f2.y, x1, fmaf(f2.z, x2, f3.z)));

        const float zz = d2 * d2;
        const float l2  = fmaf(d0, d0, fmaf(d1, d1, zz));
        const float inv = rsqrtf(l2);
        const float inv2 = inv * inv;

        // SH dot in unnormalized d-space
        const float linD = fmaf(f4.x, d1, fmaf(f4.y, d2, f4.z * d0));
        const float xy = d0 * d1;
        const float yz = d1 * d2;
        const float xz = d0 * d2;
        const float pm = fmaf(d0, d0, -(d1 * d1));   // x^2 - y^2
        const float quadD = fmaf(f4.w, xy,
                            fmaf(f5.x, yz,
                            fmaf(f5.y, zz,
                            fmaf(f5.z, xz, f5.w * pm))));
        const float rad = fmaf(linD, inv, fmaf(quadD, inv2, f3.w));

        const float r = fmaxf(rad, EPSF);
        const float len = l2 * inv;
        const float w = fmaxf(fmaf(-len, frcp(r), 1.0f), 0.f);

        wsum += w;
        const u64 ww = pk2(w, w);
        A0 = ffma2(c00, ww, A0);
        A1 = ffma2(c01, ww, A1);
        A2 = ffma2(c02, ww, A2);
        A3 = ffma2(pk2(f2.x, f2.y), ww, A3);   // {-r20,-r21}
        A4 = ffma2(pk2(f2.z, f2.w), ww, A4);   // {-r22, t0}
        A5 = ffma2(pk2(f3.x, f3.y), ww, A5);   // {t1, t2}
    }

    float m00, m10, m01, m11, m02, m12, m20, m21, m22, ta0, ta1, ta2;
    upk2(m00, m10, A0);
    upk2(m01, m11, A1);
    upk2(m02, m12, A2);
    upk2(m20, m21, A3);
    upk2(m22, ta0, A4);
    upk2(ta1, ta2, A5);

    const float ic = frcp(fmaxf(wsum, EPSF));
    const bool valid = wsum > EPSF;

    // s = tacc - (mneg x)
    const float mx0 = fmaf(m00, x0, fmaf(m01, x1, m02 * x2));
    const float mx1 = fmaf(m10, x0, fmaf(m11, x1, m12 * x2));
    const float mx2 = fmaf(m20, x0, fmaf(m21, x1, m22 * x2));
    const float o0 = valid ? (ta0 - mx0) * ic : x0;
    const float o1 = valid ? (ta1 - mx1) * ic : x1;
    const float o2 = valid ? (ta2 - mx2) * ic : x2;

    // vd_out = (mneg v) * (-ic)
    const float nic = -ic;
    const float e0 = fmaf(m00, v0, fmaf(m01, v1, m02 * v2)) * nic;
    const float e1 = fmaf(m10, v0, fmaf(m11, v1, m12 * v2)) * nic;
    const float e2 = fmaf(m20, v0, fmaf(m21, v1, m22 * v2)) * nic;
    const float g0 = valid ? e0 : v0;
    const float g1 = valid ? e1 : v1;
    const float g2 = valid ? e2 : v2;

    out[3 * i + 0] = o0;
    out[3 * i + 1] = o1;
    out[3 * i + 2] = o2;
    float* out2 = out + (size_t)3 * N;
    out2[3 * i + 0] = g0;
    out2[3 * i + 1] = g1;
    out2[3 * i + 2] = g2;
}

extern "C" void kernel_launch(void* const* d_in, const int* in_sizes, int n_in,
                              void* d_out, int out_size)
{
    const float* xyz  = (const float*)d_in[0];
    const float* vdir = (const float*)d_in[1];
    const float* T    = (const float*)d_in[2];
    const float* F    = (const float*)d_in[3];
    const float* L    = (const float*)d_in[4];
    float* out        = (float*)d_out;

    const int N = in_sizes[0] / 3;
    const int blocks = (N + THREADS - 1) / THREADS;
    shcaster_kernel<<<blocks, THREADS>>>(xyz, vdir, T, F, L, out, N);
}

// round 9
// speedup vs baseline: 1.1010x; 1.0084x over previous
#include <cuda_runtime.h>
#include <cuda_bf16.h>

#define JNT 24
#define EPSF 1e-6f
#define SH_C0 0.28209479177387814f
#define SH_C1 0.4886025119029199f
#define C20 ( 1.0925484305920792f)
#define C21 (-1.0925484305920792f)
#define C22 ( 0.31539156525252005f)
#define C23 (-1.0925484305920792f)
#define C24 ( 0.5462742152960396f)

#define THREADS 256

__device__ __forceinline__ float frcp(float x) {
    float r; asm("rcp.approx.ftz.f32 %0, %1;" : "=f"(r) : "f"(x)); return r;
}

// Shared: 6 float4 per joint
//  q0 : (-r00, -r01, -r02, L0-t0)
//  q1 : (-r10, -r11, -r12, L1-t1)
//  q2 : (-r20, -r21, -r22, L2-t2)
//  q3 : (t0, t1, t2, base)        base = SH_C0*f0 + 0.5 - C22*f6
//  q4 : (f1', f2', f3', f4')      pre-scaled SH features
//  q5 : (f5', f6'', f7', f8')     f6'' = 3*C22*f6
__global__ __launch_bounds__(THREADS)
void shcaster_kernel(const float* __restrict__ xyz,
                     const float* __restrict__ vdir,
                     const float* __restrict__ T,   // [J,4,4]
                     const float* __restrict__ F,   // [J,9]
                     const float* __restrict__ L,   // [J,3]
                     float* __restrict__ out,       // [2*N*3]
                     int N)
{
    __shared__ __align__(16) float4 sJ[JNT][6];

    const int tid = threadIdx.x;
    if (tid < JNT * 6) {
        const int j = tid / 6, k = tid % 6;
        float4 q;
        if (k < 3) {
            const float* r = T + j * 16 + k * 4;   // r0 r1 r2 t
            q = make_float4(-r[0], -r[1], -r[2], L[j * 3 + k] - r[3]);
        } else if (k == 3) {
            const float base = fmaf(SH_C0, F[j * 9 + 0], 0.5f) - C22 * F[j * 9 + 6];
            q = make_float4(T[j * 16 + 3], T[j * 16 + 7], T[j * 16 + 11], base);
        } else if (k == 4) {
            q = make_float4(-SH_C1 * F[j * 9 + 1],
                             SH_C1 * F[j * 9 + 2],
                            -SH_C1 * F[j * 9 + 3],
                             C20   * F[j * 9 + 4]);
        } else {
            q = make_float4( C21        * F[j * 9 + 5],
                             3.f * C22  * F[j * 9 + 6],
                             C23        * F[j * 9 + 7],
                             C24        * F[j * 9 + 8]);
        }
        sJ[j][k] = q;
    }
    __syncthreads();

    const int gi = blockIdx.x * blockDim.x + tid;   // pair index
    const int i0 = 2 * gi;
    if (i0 >= N) return;
    const bool hasB = (i0 + 1 < N);

    float xA0, xA1, xA2, vA0, vA1, vA2;
    float xB0 = 0.f, xB1 = 0.f, xB2 = 0.f, vB0 = 0.f, vB1 = 0.f, vB2 = 0.f;

    if (hasB) {
        const float2* xp = (const float2*)(xyz + 6 * (size_t)gi);
        const float2* vp = (const float2*)(vdir + 6 * (size_t)gi);
        const float2 a = xp[0], b = xp[1], c = xp[2];
        xA0 = a.x; xA1 = a.y; xA2 = b.x; xB0 = b.y; xB1 = c.x; xB2 = c.y;
        const float2 d = vp[0], e = vp[1], f = vp[2];
        vA0 = d.x; vA1 = d.y; vA2 = e.x; vB0 = e.y; vB1 = f.x; vB2 = f.y;
    } else {
        xA0 = xyz[3 * i0 + 0]; xA1 = xyz[3 * i0 + 1]; xA2 = xyz[3 * i0 + 2];
        vA0 = vdir[3 * i0 + 0]; vA1 = vdir[3 * i0 + 1]; vA2 = vdir[3 * i0 + 2];
    }

    float wsA = 0.f, wsB = 0.f;
    float taA0 = 0.f, taA1 = 0.f, taA2 = 0.f;
    float taB0 = 0.f, taB1 = 0.f, taB2 = 0.f;
    float mA00 = 0.f, mA01 = 0.f, mA02 = 0.f;
    float mA10 = 0.f, mA11 = 0.f, mA12 = 0.f;
    float mA20 = 0.f, mA21 = 0.f, mA22 = 0.f;
    float mB00 = 0.f, mB01 = 0.f, mB02 = 0.f;
    float mB10 = 0.f, mB11 = 0.f, mB12 = 0.f;
    float mB20 = 0.f, mB21 = 0.f, mB22 = 0.f;

#pragma unroll
    for (int j = 0; j < JNT; j++) {
        const float4 q0 = sJ[j][0];
        const float4 q1 = sJ[j][1];
        const float4 q2 = sJ[j][2];
        const float4 q3 = sJ[j][3];
        const float4 q4 = sJ[j][4];
        const float4 q5 = sJ[j][5];

        // ---- point A ----
        const float dA0 = fmaf(q0.x, xA0, fmaf(q0.y, xA1, fmaf(q0.z, xA2, q0.w)));
        const float dA1 = fmaf(q1.x, xA0, fmaf(q1.y, xA1, fmaf(q1.z, xA2, q1.w)));
        const float dA2 = fmaf(q2.x, xA0, fmaf(q2.y, xA1, fmaf(q2.z, xA2, q2.w)));
        // ---- point B ----
        const float dB0 = fmaf(q0.x, xB0, fmaf(q0.y, xB1, fmaf(q0.z, xB2, q0.w)));
        const float dB1 = fmaf(q1.x, xB0, fmaf(q1.y, xB1, fmaf(q1.z, xB2, q1.w)));
        const float dB2 = fmaf(q2.x, xB0, fmaf(q2.y, xB1, fmaf(q2.z, xB2, q2.w)));

        const float zzA = dA2 * dA2;
        const float zzB = dB2 * dB2;
        const float l2A = fmaf(dA0, dA0, fmaf(dA1, dA1, zzA));
        const float l2B = fmaf(dB0, dB0, fmaf(dB1, dB1, zzB));
        const float invA = rsqrtf(l2A);
        const float invB = rsqrtf(l2B);
        const float inv2A = invA * invA;
        const float inv2B = invB * invB;

        const float linA = fmaf(q4.x, dA1, fmaf(q4.y, dA2, q4.z * dA0));
        const float linB = fmaf(q4.x, dB1, fmaf(q4.y, dB2, q4.z * dB0));
        const float xyA = dA0 * dA1, xyB = dB0 * dB1;
        const float yzA = dA1 * dA2, yzB = dB1 * dB2;
        const float xzA = dA0 * dA2, xzB = dB0 * dB2;
        const float pmA = fmaf(dA0, dA0, -(dA1 * dA1));
        const float pmB = fmaf(dB0, dB0, -(dB1 * dB1));
        const float quadA = fmaf(q4.w, xyA, fmaf(q5.x, yzA,
                            fmaf(q5.y, zzA, fmaf(q5.z, xzA, q5.w * pmA))));
        const float quadB = fmaf(q4.w, xyB, fmaf(q5.x, yzB,
                            fmaf(q5.y, zzB, fmaf(q5.z, xzB, q5.w * pmB))));
        const float radA = fmaf(linA, invA, fmaf(quadA, inv2A, q3.w));
        const float radB = fmaf(linB, invB, fmaf(quadB, inv2B, q3.w));

        const float rA = fmaxf(radA, EPSF);
        const float rB = fmaxf(radB, EPSF);
        const float lenA = l2A * invA;
        const float lenB = l2B * invB;
        const float wA = fmaxf(fmaf(-lenA, frcp(rA), 1.0f), 0.f);
        const float wB = fmaxf(fmaf(-lenB, frcp(rB), 1.0f), 0.f);

        wsA += wA;
        wsB += wB;
        taA0 = fmaf(wA, q3.x, taA0); taA1 = fmaf(wA, q3.y, taA1); taA2 = fmaf(wA, q3.z, taA2);
        taB0 = fmaf(wB, q3.x, taB0); taB1 = fmaf(wB, q3.y, taB1); taB2 = fmaf(wB, q3.z, taB2);
        mA00 = fmaf(wA, q0.x, mA00); mA01 = fmaf(wA, q0.y, mA01); mA02 = fmaf(wA, q0.z, mA02);
        mA10 = fmaf(wA, q1.x, mA10); mA11 = fmaf(wA, q1.y, mA11); mA12 = fmaf(wA, q1.z, mA12);
        mA20 = fmaf(wA, q2.x, mA20); mA21 = fmaf(wA, q2.y, mA21); mA22 = fmaf(wA, q2.z, mA22);
        mB00 = fmaf(wB, q0.x, mB00); mB01 = fmaf(wB, q0.y, mB01); mB02 = fmaf(wB, q0.z, mB02);
        mB10 = fmaf(wB, q1.x, mB10); mB11 = fmaf(wB, q1.y, mB11); mB12 = fmaf(wB, q1.z, mB12);
        mB20 = fmaf(wB, q2.x, mB20); mB21 = fmaf(wB, q2.y, mB21); mB22 = fmaf(wB, q2.z, mB22);
    }

    // ---- epilogue A ----
    const float icA = frcp(fmaxf(wsA, EPSF));
    const bool valA = wsA > EPSF;
    const float mxA0 = fmaf(mA00, xA0, fmaf(mA01, xA1, mA02 * xA2));
    const float mxA1 = fmaf(mA10, xA0, fmaf(mA11, xA1, mA12 * xA2));
    const float mxA2 = fmaf(mA20, xA0, fmaf(mA21, xA1, mA22 * xA2));
    const float oA0 = valA ? (taA0 - mxA0) * icA : xA0;
    const float oA1 = valA ? (taA1 - mxA1) * icA : xA1;
    const float oA2 = valA ? (taA2 - mxA2) * icA : xA2;
    const float nicA = -icA;
    const float eA0 = fmaf(mA00, vA0, fmaf(mA01, vA1, mA02 * vA2)) * nicA;
    const float eA1 = fmaf(mA10, vA0, fmaf(mA11, vA1, mA12 * vA2)) * nicA;
    const float eA2 = fmaf(mA20, vA0, fmaf(mA21, vA1, mA22 * vA2)) * nicA;
    const float gA0 = valA ? eA0 : vA0;
    const float gA1 = valA ? eA1 : vA1;
    const float gA2 = valA ? eA2 : vA2;

    float* o1p = out + 6 * (size_t)gi;
    float* o2p = out + 3 * (size_t)N + 6 * (size_t)gi;

    if (hasB) {
        // ---- epilogue B ----
        const float icB = frcp(fmaxf(wsB, EPSF));
        const bool valB = wsB > EPSF;
        const float mxB0 = fmaf(mB00, xB0, fmaf(mB01, xB1, mB02 * xB2));
        const float mxB1 = fmaf(mB10, xB0, fmaf(mB11, xB1, mB12 * xB2));
        const float mxB2 = fmaf(mB20, xB0, fmaf(mB21, xB1, mB22 * xB2));
        const float oB0 = valB ? (taB0 - mxB0) * icB : xB0;
        const float oB1 = valB ? (taB1 - mxB1) * icB : xB1;
        const float oB2 = valB ? (taB2 - mxB2) * icB : xB2;
        const float nicB = -icB;
        const float eB0 = fmaf(mB00, vB0, fmaf(mB01, vB1, mB02 * vB2)) * nicB;
        const float eB1 = fmaf(mB10, vB0, fmaf(mB11, vB1, mB12 * vB2)) * nicB;
        const float eB2 = fmaf(mB20, vB0, fmaf(mB21, vB1, mB22 * vB2)) * nicB;
        const float gB0 = valB ? eB0 : vB0;
        const float gB1 = valB ? eB1 : vB1;
        const float gB2 = valB ? eB2 : vB2;

        float2* o1v = (float2*)o1p;
        float2* o2v = (float2*)o2p;
        o1v[0] = make_float2(oA0, oA1);
        o1v[1] = make_float2(oA2, oB0);
        o1v[2] = make_float2(oB1, oB2);
        o2v[0] = make_float2(gA0, gA1);
        o2v[1] = make_float2(gA2, gB0);
        o2v[2] = make_float2(gB1, gB2);
    } else {
        o1p[0] = oA0; o1p[1] = oA1; o1p[2] = oA2;
        o2p[0] = gA0; o2p[1] = gA1; o2p[2] = gA2;
    }
}

extern "C" void kernel_launch(void* const* d_in, const int* in_sizes, int n_in,
                              void* d_out, int out_size)
{
    const float* xyz  = (const float*)d_in[0];
    const float* vdir = (const float*)d_in[1];
    const float* T    = (const float*)d_in[2];
    const float* F    = (const float*)d_in[3];
    const float* L    = (const float*)d_in[4];
    float* out        = (float*)d_out;

    const int N = in_sizes[0] / 3;
    const int nPairs = (N + 1) / 2;
    const int blocks = (nPairs + THREADS - 1) / THREADS;
    shcaster_kernel<<<blocks, THREADS>>>(xyz, vdir, T, F, L, out, N);
}

// round 10
// speedup vs baseline: 1.1295x; 1.0259x over previous
#include <cuda_runtime.h>
#include <cuda_bf16.h>

#define JNT 24
#define EPSF 1e-6f
#define SH_C0 0.28209479177387814f
#define SH_C1 0.4886025119029199f
#define C20 ( 1.0925484305920792f)
#define C21 (-1.0925484305920792f)
#define C22 ( 0.31539156525252005f)
#define C23 (-1.0925484305920792f)
#define C24 ( 0.5462742152960396f)

#define THREADS 256

typedef unsigned long long u64;

__device__ __forceinline__ float frcp(float x) {
    float r; asm("rcp.approx.ftz.f32 %0, %1;" : "=f"(r) : "f"(x)); return r;
}
__device__ __forceinline__ u64 pk2(float lo, float hi) {
    u64 r; asm("mov.b64 %0, {%1, %2};" : "=l"(r) : "f"(lo), "f"(hi)); return r;
}
__device__ __forceinline__ void upk2(float& lo, float& hi, u64 v) {
    asm("mov.b64 {%0, %1}, %2;" : "=f"(lo), "=f"(hi) : "l"(v));
}
__device__ __forceinline__ u64 ffma2(u64 a, u64 b, u64 c) {
    u64 d; asm("fma.rn.f32x2 %0, %1, %2, %3;" : "=l"(d) : "l"(a), "l"(b), "l"(c)); return d;
}

// Shared: 6 float4 per joint, pair-aliased layout (no duplication):
//  s0: (-r00, -r10, -r01, -r11)   pairs {-r00,-r10}, {-r01,-r11}
//  s1: (-r02, -r12, L0-t0, L1-t1) pairs {-r02,-r12}, {L0-t0,L1-t1}
//  s2: (-r20, -r21, -r22, t0)     pairs {-r20,-r21}, {-r22,t0}
//  s3: (t1, t2, L2-t2, base)      pair  {t1,t2},  scalars L2-t2, base
//  s4: (f1', f2', f3', f4')       pre-scaled SH features
//  s5: (f5', f6'', f7', f8')      f6'' = 3*C22*f6
__global__ __launch_bounds__(THREADS)
void shcaster_kernel(const float* __restrict__ xyz,
                     const float* __restrict__ vdir,
                     const float* __restrict__ T,   // [J,4,4]
                     const float* __restrict__ F,   // [J,9]
                     const float* __restrict__ L,   // [J,3]
                     float* __restrict__ out,       // [2*N*3]
                     int N)
{
    __shared__ __align__(16) float4 sJ[JNT][6];

    const int tid = threadIdx.x;
    if (tid < JNT * 6) {
        const int j = tid / 6, k = tid % 6;
        const float* t = T + j * 16;   // row-major: r00 r01 r02 t0 | r10.. t1 | r20.. t2
        float4 q;
        if (k == 0) {
            q = make_float4(-t[0], -t[4], -t[1], -t[5]);
        } else if (k == 1) {
            q = make_float4(-t[2], -t[6], L[j*3+0] - t[3], L[j*3+1] - t[7]);
        } else if (k == 2) {
            q = make_float4(-t[8], -t[9], -t[10], t[3]);
        } else if (k == 3) {
            const float base = fmaf(SH_C0, F[j*9+0], 0.5f) - C22 * F[j*9+6];
            q = make_float4(t[7], t[11], L[j*3+2] - t[11], base);
        } else if (k == 4) {
            q = make_float4(-SH_C1 * F[j*9+1],
                             SH_C1 * F[j*9+2],
                            -SH_C1 * F[j*9+3],
                             C20   * F[j*9+4]);
        } else {
            q = make_float4( C21       * F[j*9+5],
                             3.f * C22 * F[j*9+6],
                             C23       * F[j*9+7],
                             C24       * F[j*9+8]);
        }
        sJ[j][k] = q;
    }
    __syncthreads();

    const int i = blockIdx.x * blockDim.x + tid;
    if (i >= N) return;

    const float x0 = xyz[3 * i + 0];
    const float x1 = xyz[3 * i + 1];
    const float x2 = xyz[3 * i + 2];
    const float v0 = vdir[3 * i + 0];
    const float v1 = vdir[3 * i + 1];
    const float v2 = vdir[3 * i + 2];

    // broadcast-packed point coords (hoisted)
    const u64 X0p = pk2(x0, x0);
    const u64 X1p = pk2(x1, x1);
    const u64 X2p = pk2(x2, x2);

    float wsum = 0.f;
    u64 A0 = 0ull;   // {m00, m10}    m = sum w * (-R)
    u64 A1 = 0ull;   // {m01, m11}
    u64 A2 = 0ull;   // {m02, m12}
    u64 A3 = 0ull;   // {m20, m21}
    u64 A4 = 0ull;   // {m22, ta0}    ta = sum w * t
    u64 A5 = 0ull;   // {ta1, ta2}

#pragma unroll
    for (int j = 0; j < JNT; j++) {
        const ulonglong2 u0 = *(const ulonglong2*)&sJ[j][0];  // {P00, P01}
        const ulonglong2 u1 = *(const ulonglong2*)&sJ[j][1];  // {P02, PL01}
        const ulonglong2 u2 = *(const ulonglong2*)&sJ[j][2];  // {{-r20,-r21},{-r22,t0}}
        const ulonglong2 u3 = *(const ulonglong2*)&sJ[j][3];  // {{t1,t2},{L2-t2,base}}
        const float4 q4 = sJ[j][4];
        const float4 q5 = sJ[j][5];

        // d0,d1 = (L-t) - Rx  (column-pair packed)
        const u64 d01 = ffma2(u0.x, X0p, ffma2(u0.y, X1p, ffma2(u1.x, X2p, u1.y)));
        float d0, d1;
        upk2(d0, d1, d01);

        float nr20, nr21, nr22, t0s, L2t2, base;
        upk2(nr20, nr21, u2.x);
        upk2(nr22, t0s,  u2.y);
        upk2(L2t2, base, u3.y);
        (void)t0s;

        const float d2 = fmaf(nr20, x0, fmaf(nr21, x1, fmaf(nr22, x2, L2t2)));

        const float zz = d2 * d2;
        const float l2  = fmaf(d0, d0, fmaf(d1, d1, zz));
        const float inv = rsqrtf(l2);

        // SH dot in unnormalized d-space, inv2-free chain:
        // rad = ((quadD * inv + linD) * inv) + base
        const float linD = fmaf(q4.x, d1, fmaf(q4.y, d2, q4.z * d0));
        const float xy = d0 * d1;
        const float yz = d1 * d2;
        const float xz = d0 * d2;
        const float pm = fmaf(d0, d0, -(d1 * d1));   // x^2 - y^2
        const float quadD = fmaf(q4.w, xy,
                            fmaf(q5.x, yz,
                            fmaf(q5.y, zz,
                            fmaf(q5.z, xz, q5.w * pm))));
        const float tq  = fmaf(quadD, inv, linD);
        const float rad = fmaf(tq, inv, base);

        const float r = fmaxf(rad, EPSF);
        const float len = l2 * inv;
        const float w = fmaxf(fmaf(-len, frcp(r), 1.0f), 0.f);

        wsum += w;
        const u64 ww = pk2(w, w);
        A0 = ffma2(u0.x, ww, A0);   // {m00, m10}
        A1 = ffma2(u0.y, ww, A1);   // {m01, m11}
        A2 = ffma2(u1.x, ww, A2);   // {m02, m12}
        A3 = ffma2(u2.x, ww, A3);   // {m20, m21}
        A4 = ffma2(u2.y, ww, A4);   // {m22, ta0}
        A5 = ffma2(u3.x, ww, A5);   // {ta1, ta2}
    }

    float m00, m10, m01, m11, m02, m12, m20, m21, m22, ta0, ta1, ta2;
    upk2(m00, m10, A0);
    upk2(m01, m11, A1);
    upk2(m02, m12, A2);
    upk2(m20, m21, A3);
    upk2(m22, ta0, A4);
    upk2(ta1, ta2, A5);

    const float ic = frcp(fmaxf(wsum, EPSF));
    const bool valid = wsum > EPSF;

    // s = tacc - (mneg x)
    const float mx0 = fmaf(m00, x0, fmaf(m01, x1, m02 * x2));
    const float mx1 = fmaf(m10, x0, fmaf(m11, x1, m12 * x2));
    const float mx2 = fmaf(m20, x0, fmaf(m21, x1, m22 * x2));
    const float o0 = valid ? (ta0 - mx0) * ic : x0;
    const float o1 = valid ? (ta1 - mx1) * ic : x1;
    const float o2 = valid ? (ta2 - mx2) * ic : x2;

    // vd_out = (mneg v) * (-ic)
    const float nic = -ic;
    const float e0 = fmaf(m00, v0, fmaf(m01, v1, m02 * v2)) * nic;
    const float e1 = fmaf(m10, v0, fmaf(m11, v1, m12 * v2)) * nic;
    const float e2 = fmaf(m20, v0, fmaf(m21, v1, m22 * v2)) * nic;
    const float g0 = valid ? e0 : v0;
    const float g1 = valid ? e1 : v1;
    const float g2 = valid ? e2 : v2;

    out[3 * i + 0] = o0;
    out[3 * i + 1] = o1;
    out[3 * i + 2] = o2;
    float* out2 = out + (size_t)3 * N;
    out2[3 * i + 0] = g0;
    out2[3 * i + 1] = g1;
    out2[3 * i + 2] = g2;
}

extern "C" void kernel_launch(void* const* d_in, const int* in_sizes, int n_in,
                              void* d_out, int out_size)
{
    const float* xyz  = (const float*)d_in[0];
    const float* vdir = (const float*)d_in[1];
    const float* T    = (const float*)d_in[2];
    const float* F    = (const float*)d_in[3];
    const float* L    = (const float*)d_in[4];
    float* out        = (float*)d_out;

    const int N = in_sizes[0] / 3;
    const int blocks = (N + THREADS - 1) / THREADS;
    shcaster_kernel<<<blocks, THREADS>>>(xyz, vdir, T, F, L, out, N);
}